// round 9
// baseline (speedup 1.0000x reference)
#include <cuda_runtime.h>
#include <cuda_fp16.h>
#include <cstdint>

// QFM: out[b] = sum_f linear_w[x[b,f]+f*V] + bias
//             + 0.5 * sum_d ( (sum_f emb[b,f,d])^2 - sum_f emb[b,f,d]^2 )
// B=16384, F=39, V=100000, D=128, K=256, M=8, Q=16.
//
// R8: SMEM-staged codebook slices (fp16, 64KB per feature), cluster-4
// multicast cp.async.bulk, double-buffered mbarrier pipeline. Gathers are
// conflict-free LDS.128 (2 rows x 8 segments per instr, deterministic
// bank quads). Codes pre-staged as bytes in SMEM. This removes the
// 312-wavefront/row codebook gather load from the L1tex pipe.

constexpr int F = 39;
constexpr int V = 100000;
constexpr int K = 256;
constexpr int D = 128;
constexpr int CB4 = F * K * D / 4;       // uint2 count (4 halfs each)

constexpr int ROWS_PER_BLOCK = 128;      // 32 warps x 4 rows
constexpr int THREADS = 1024;
constexpr int CLUSTER = 4;

constexpr int SLICE_BYTES = K * D * 2;   // 65536 (one feature, fp16)

// dynamic smem layout
constexpr int BUF0_OFF  = 0;
constexpr int BUF1_OFF  = SLICE_BYTES;                   // 65536
constexpr int CODE_OFF  = 2 * SLICE_BYTES;               // 131072
constexpr int CODE_BYTES = F * ROWS_PER_BLOCK * 8;       // 39936
constexpr int X_OFF     = CODE_OFF + CODE_BYTES;         // 171008
constexpr int X_BYTES   = ROWS_PER_BLOCK * F * 4;        // 19968
constexpr int MBAR_OFF  = X_OFF + X_BYTES;               // 190976
// full0 +0, full1 +8, empty0 +16, empty1 +24
constexpr int SMEM_TOTAL = MBAR_OFF + 32;                // 191008

__device__ uint2 g_cbh[CB4];             // fp16 codebooks, 2.56 MB scratch

__device__ __forceinline__ unsigned h2_bits(__half2 h) {
    return *reinterpret_cast<unsigned*>(&h);
}
__device__ __forceinline__ __half2 bits_h2(unsigned u) {
    return *reinterpret_cast<__half2*>(&u);
}

__global__ __launch_bounds__(256)
void cvt_kernel(const float4* __restrict__ src)
{
    const int i = blockIdx.x * blockDim.x + threadIdx.x;
    if (i < CB4) {
        const float4 v = src[i];
        uint2 o;
        o.x = h2_bits(__floats2half2_rn(v.x, v.y));
        o.y = h2_bits(__floats2half2_rn(v.z, v.w));
        g_cbh[i] = o;
    }
}

// ---------------- PTX helpers ----------------
__device__ __forceinline__ uint32_t smem_u32(const void* p) {
    uint32_t a;
    asm("{ .reg .u64 t; cvta.to.shared.u64 t, %1; cvt.u32.u64 %0, t; }"
        : "=r"(a) : "l"(p));
    return a;
}
__device__ __forceinline__ uint32_t ctarank() {
    uint32_t r; asm("mov.u32 %0, %%cluster_ctarank;" : "=r"(r)); return r;
}
#define MBAR_INIT(a, n) \
    asm volatile("mbarrier.init.shared.b64 [%0], %1;" :: "r"(a), "r"((uint32_t)(n)) : "memory")
#define MBAR_EXPECT_TX(a, b) \
    asm volatile("mbarrier.arrive.expect_tx.shared.b64 _, [%0], %1;" :: "r"(a), "r"((uint32_t)(b)) : "memory")
#define MBAR_ARRIVE_RANK0(a) \
    asm volatile("{ .reg .b32 ra; mapa.shared::cluster.u32 ra, %0, 0;" \
                 "  mbarrier.arrive.release.cluster.shared::cluster.b64 _, [ra]; }" \
                 :: "r"(a) : "memory")
__device__ __forceinline__ void mbar_wait(uint32_t a, uint32_t parity) {
    asm volatile(
        "{ .reg .pred P;\n"
        "W_%=:\n"
        " mbarrier.try_wait.parity.acquire.cta.shared::cta.b64 P, [%0], %1, 0x989680;\n"
        " @P bra.uni D_%=;\n"
        " bra.uni W_%=;\n"
        "D_%=: }"
        :: "r"(a), "r"(parity) : "memory");
}
#define CLUSTER_SYNC() do { \
    asm volatile("barrier.cluster.arrive.aligned;" ::: "memory"); \
    asm volatile("barrier.cluster.wait.aligned;"   ::: "memory"); } while (0)

__device__ __forceinline__ void bulk_mcast(uint32_t dst, const void* src,
                                           uint32_t bytes, uint32_t mbar,
                                           uint16_t mask) {
    asm volatile(
        "cp.async.bulk.shared::cluster.global.mbarrier::complete_tx::bytes"
        ".multicast::cluster [%0], [%1], %2, [%3], %4;"
        :: "r"(dst), "l"(src), "r"(bytes), "r"(mbar), "h"(mask) : "memory");
}
__device__ __forceinline__ void lds128(uint4& d, uint32_t a) {
    asm volatile("ld.shared.v4.u32 {%0,%1,%2,%3}, [%4];"
                 : "=r"(d.x), "=r"(d.y), "=r"(d.z), "=r"(d.w) : "r"(a));
}
__device__ __forceinline__ unsigned lds_u8(uint32_t a) {
    unsigned v; asm volatile("ld.shared.u8 %0, [%1];" : "=r"(v) : "r"(a)); return v;
}
__device__ __forceinline__ void sts_u8(uint32_t a, unsigned v) {
    asm volatile("st.shared.u8 [%0], %1;" :: "r"(a), "r"(v) : "memory");
}
__device__ __forceinline__ int lds_s32(uint32_t a) {
    int v; asm volatile("ld.shared.b32 %0, [%1];" : "=r"(v) : "r"(a)); return v;
}

// ---------------- main kernel ----------------
__global__ __launch_bounds__(THREADS, 1) __cluster_dims__(CLUSTER, 1, 1)
void qfm_kernel(const int*   __restrict__ x,           // (B, F)
                const int*   __restrict__ cb_index,    // (F*V, 8)
                const float* __restrict__ linear_w,    // (F*V)
                const float* __restrict__ linear_bias, // (1)
                float*       __restrict__ out)         // (B)
{
    extern __shared__ char smem[];
    const uint32_t sb   = smem_u32(smem);
    const int tid  = threadIdx.x;
    const int lane = tid & 31;
    const int w    = tid >> 5;                  // warp 0..31
    const unsigned FULL = 0xffffffffu;
    const bool leader = (ctarank() == 0);

    const uint32_t full0  = sb + MBAR_OFF + 0;
    const uint32_t full1  = sb + MBAR_OFF + 8;
    const uint32_t empty0 = sb + MBAR_OFF + 16;
    const uint32_t empty1 = sb + MBAR_OFF + 24;

    // ---- init barriers + arm first two stages
    if (tid == 0) {
        MBAR_INIT(full0, 1);  MBAR_INIT(full1, 1);
        MBAR_INIT(empty0, CLUSTER); MBAR_INIT(empty1, CLUSTER);
        MBAR_EXPECT_TX(full0, SLICE_BYTES);
        MBAR_EXPECT_TX(full1, SLICE_BYTES);
    }

    // ---- stage x tile into smem (coalesced)
    const int row0g = blockIdx.x * ROWS_PER_BLOCK;     // exact fit: B = 128*128
    {
        const int* xs = x + row0g * F;
        int* xd = reinterpret_cast<int*>(smem + X_OFF);
        for (int i = tid; i < ROWS_PER_BLOCK * F; i += THREADS)
            xd[i] = xs[i];
    }
    __syncthreads();
    CLUSTER_SYNC();                                    // all CTAs armed

    // ---- leader issues first two multicast stages
    if (leader && tid == 0) {
        bulk_mcast(sb + BUF0_OFF, (const char*)g_cbh + 0 * SLICE_BYTES,
                   SLICE_BYTES, full0, 0xF);
        bulk_mcast(sb + BUF1_OFF, (const char*)g_cbh + 1 * SLICE_BYTES,
                   SLICE_BYTES, full1, 0xF);
    }

    // ---- Phase A: codes (bytes to smem) + linear accumulation.
    // Lane L: local row r = L>>3 of this warp, sub-codebook mm = L&7.
    float lin = 0.f;
    {
        const int r  = lane >> 3;
        const int mm = lane & 7;
        const int rowl = 4 * w + r;
        #pragma unroll 1
        for (int f = 0; f < F; ++f) {
            const int xi = lds_s32(sb + X_OFF + (rowl * F + f) * 4);
            const int xo = f * V + xi;
            const unsigned code = (unsigned)__ldcs(&cb_index[xo * 8 + mm]);
            sts_u8(sb + CODE_OFF + (f * ROWS_PER_BLOCK + rowl) * 8 + mm, code);
            if (mm == 0) lin += __ldcs(&linear_w[xo]);
        }
    }
    __syncthreads();                                   // codes visible

    // ---- Phase B: f-loop over staged slices.
    // Lane t: half h = t>>4 (row within pair), m = (t&15)>>1, j = t&1.
    // Pair 0 covers rows 4w + h ; pair 1 covers rows 4w + 2 + h.
    const int h = lane >> 4;
    const int m = (lane & 15) >> 1;
    const int j = lane & 1;
    const uint32_t seg_off = (uint32_t)((m << 5) + (j << 4));
    const int rA = 4 * w + h;          // local row, pair 0
    const int rB = rA + 2;             // local row, pair 1

    float s0[8], q0[8], s1[8], q1[8];
    #pragma unroll
    for (int k = 0; k < 8; ++k) { s0[k]=0.f; q0[k]=0.f; s1[k]=0.f; q1[k]=0.f; }

    #pragma unroll 1
    for (int f = 0; f < F; ++f) {
        const int slot = f & 1;
        const uint32_t fullb  = slot ? full1  : full0;
        const uint32_t emptyb = slot ? empty1 : empty0;
        const uint32_t parity = (uint32_t)((f >> 1) & 1);
        mbar_wait(fullb, parity);

        const uint32_t buf = sb + (slot ? BUF1_OFF : BUF0_OFF);
        const uint32_t cbase = sb + CODE_OFF + (uint32_t)f * (ROWS_PER_BLOCK * 8);

        const unsigned cA = lds_u8(cbase + rA * 8 + m);
        const unsigned cB = lds_u8(cbase + rB * 8 + m);
        uint4 dA, dB;
        lds128(dA, buf + (cA << 8) + seg_off);
        lds128(dB, buf + (cB << 8) + seg_off);

        const unsigned* pa = reinterpret_cast<const unsigned*>(&dA);
        const unsigned* pb = reinterpret_cast<const unsigned*>(&dB);
        #pragma unroll
        for (int k = 0; k < 4; ++k) {
            const float2 ea = __half22float2(bits_h2(pa[k]));
            s0[2*k]   += ea.x;  s0[2*k+1] += ea.y;
            q0[2*k]   = fmaf(ea.x, ea.x, q0[2*k]);
            q0[2*k+1] = fmaf(ea.y, ea.y, q0[2*k+1]);
            const float2 eb = __half22float2(bits_h2(pb[k]));
            s1[2*k]   += eb.x;  s1[2*k+1] += eb.y;
            q1[2*k]   = fmaf(eb.x, eb.x, q1[2*k]);
            q1[2*k+1] = fmaf(eb.y, eb.y, q1[2*k+1]);
        }

        __syncthreads();                               // block done with buf
        if (tid == 0) {
            if (f + 2 < F) MBAR_EXPECT_TX(fullb, SLICE_BYTES);  // re-arm slot
            MBAR_ARRIVE_RANK0(emptyb);                 // tell leader we're done
            if (leader && f + 2 < F) {
                mbar_wait(emptyb, parity);             // all 4 CTAs done
                bulk_mcast(buf, (const char*)g_cbh + (size_t)(f + 2) * SLICE_BYTES,
                           SLICE_BYTES, fullb, 0xF);
            }
        }
    }

    // ---- epilogue: fm per lane (8 dims x 2 rows) -> half-warp reduce.
    float cA = 0.f, cB = 0.f;
    #pragma unroll
    for (int k = 0; k < 8; ++k) {
        cA += 0.5f * fmaf(s0[k], s0[k], -q0[k]);
        cB += 0.5f * fmaf(s1[k], s1[k], -q1[k]);
    }
    #pragma unroll
    for (int o = 1; o < 16; o <<= 1) {
        cA += __shfl_xor_sync(FULL, cA, o);
        cB += __shfl_xor_sync(FULL, cB, o);
    }
    // lin(row 4w+r) lives at lane 8r (Phase A layout)
    const float linA = __shfl_sync(FULL, lin, 8 * h);
    const float linB = __shfl_sync(FULL, lin, 8 * h + 16);
    if ((lane & 15) == 0) {
        const float bias = __ldg(linear_bias);
        out[row0g + rA] = cA + linA + bias;
        out[row0g + rB] = cB + linB + bias;
    }

    CLUSTER_SYNC();                                    // no early exit vs peers
}

extern "C" void kernel_launch(void* const* d_in, const int* in_sizes, int n_in,
                              void* d_out, int out_size)
{
    const int*    x         = (const int*)   d_in[0];
    const float4* codebooks = (const float4*)d_in[1];
    const int*    cb_index  = (const int*)   d_in[2];
    const float*  linear_w  = (const float*) d_in[3];
    const float*  lbias     = (const float*) d_in[4];
    float*        out       = (float*)       d_out;

    // Prologue: fp32 -> fp16 codebook conversion (L2-resident, ~1 us).
    cvt_kernel<<<(CB4 + 255) / 256, 256>>>(codebooks);

    static bool attr_set = false;
    if (!attr_set) {   // idempotent; harmless if repeated, but do once
        cudaFuncSetAttribute(qfm_kernel,
                             cudaFuncAttributeMaxDynamicSharedMemorySize,
                             SMEM_TOTAL);
        attr_set = true;
    }

    const int blocks = out_size / ROWS_PER_BLOCK;      // 16384/128 = 128
    qfm_kernel<<<blocks, THREADS, SMEM_TOTAL>>>(x, cb_index, linear_w, lbias, out);
}

// round 10
// speedup vs baseline: 1.0056x; 1.0056x over previous
#include <cuda_runtime.h>
#include <cuda_fp16.h>
#include <cstdint>

// QFM: out[b] = sum_f linear_w[x[b,f]+f*V] + bias
//             + 0.5 * sum_d ( (sum_f emb[b,f,d])^2 - sum_f emb[b,f,d]^2 )
// B=16384, F=39, V=100000, D=128, K=256, M=8, Q=16.
//
// R8: SMEM-staged codebook slices (fp16, 64KB per feature), cluster-4
// multicast cp.async.bulk, double-buffered mbarrier pipeline. Gathers are
// conflict-free LDS.128 (2 rows x 8 segments per instr, deterministic
// bank quads). Codes pre-staged as bytes in SMEM. This removes the
// 312-wavefront/row codebook gather load from the L1tex pipe.

constexpr int F = 39;
constexpr int V = 100000;
constexpr int K = 256;
constexpr int D = 128;
constexpr int CB4 = F * K * D / 4;       // uint2 count (4 halfs each)

constexpr int ROWS_PER_BLOCK = 128;      // 32 warps x 4 rows
constexpr int THREADS = 1024;
constexpr int CLUSTER = 4;

constexpr int SLICE_BYTES = K * D * 2;   // 65536 (one feature, fp16)

// dynamic smem layout
constexpr int BUF0_OFF  = 0;
constexpr int BUF1_OFF  = SLICE_BYTES;                   // 65536
constexpr int CODE_OFF  = 2 * SLICE_BYTES;               // 131072
constexpr int CODE_BYTES = F * ROWS_PER_BLOCK * 8;       // 39936
constexpr int X_OFF     = CODE_OFF + CODE_BYTES;         // 171008
constexpr int X_BYTES   = ROWS_PER_BLOCK * F * 4;        // 19968
constexpr int MBAR_OFF  = X_OFF + X_BYTES;               // 190976
// full0 +0, full1 +8, empty0 +16, empty1 +24
constexpr int SMEM_TOTAL = MBAR_OFF + 32;                // 191008

__device__ uint2 g_cbh[CB4];             // fp16 codebooks, 2.56 MB scratch

__device__ __forceinline__ unsigned h2_bits(__half2 h) {
    return *reinterpret_cast<unsigned*>(&h);
}
__device__ __forceinline__ __half2 bits_h2(unsigned u) {
    return *reinterpret_cast<__half2*>(&u);
}

__global__ __launch_bounds__(256)
void cvt_kernel(const float4* __restrict__ src)
{
    const int i = blockIdx.x * blockDim.x + threadIdx.x;
    if (i < CB4) {
        const float4 v = src[i];
        uint2 o;
        o.x = h2_bits(__floats2half2_rn(v.x, v.y));
        o.y = h2_bits(__floats2half2_rn(v.z, v.w));
        g_cbh[i] = o;
    }
}

// ---------------- PTX helpers ----------------
__device__ __forceinline__ uint32_t smem_u32(const void* p) {
    uint32_t a;
    asm("{ .reg .u64 t; cvta.to.shared.u64 t, %1; cvt.u32.u64 %0, t; }"
        : "=r"(a) : "l"(p));
    return a;
}
__device__ __forceinline__ uint32_t ctarank() {
    uint32_t r; asm("mov.u32 %0, %%cluster_ctarank;" : "=r"(r)); return r;
}
#define MBAR_INIT(a, n) \
    asm volatile("mbarrier.init.shared.b64 [%0], %1;" :: "r"(a), "r"((uint32_t)(n)) : "memory")
#define MBAR_EXPECT_TX(a, b) \
    asm volatile("mbarrier.arrive.expect_tx.shared.b64 _, [%0], %1;" :: "r"(a), "r"((uint32_t)(b)) : "memory")
#define MBAR_ARRIVE_RANK0(a) \
    asm volatile("{ .reg .b32 ra; mapa.shared::cluster.u32 ra, %0, 0;" \
                 "  mbarrier.arrive.release.cluster.shared::cluster.b64 _, [ra]; }" \
                 :: "r"(a) : "memory")
__device__ __forceinline__ void mbar_wait(uint32_t a, uint32_t parity) {
    asm volatile(
        "{ .reg .pred P;\n"
        "W_%=:\n"
        " mbarrier.try_wait.parity.acquire.cta.shared::cta.b64 P, [%0], %1, 0x989680;\n"
        " @P bra.uni D_%=;\n"
        " bra.uni W_%=;\n"
        "D_%=: }"
        :: "r"(a), "r"(parity) : "memory");
}
#define CLUSTER_SYNC() do { \
    asm volatile("barrier.cluster.arrive.aligned;" ::: "memory"); \
    asm volatile("barrier.cluster.wait.aligned;"   ::: "memory"); } while (0)

__device__ __forceinline__ void bulk_mcast(uint32_t dst, const void* src,
                                           uint32_t bytes, uint32_t mbar,
                                           uint16_t mask) {
    asm volatile(
        "cp.async.bulk.shared::cluster.global.mbarrier::complete_tx::bytes"
        ".multicast::cluster [%0], [%1], %2, [%3], %4;"
        :: "r"(dst), "l"(src), "r"(bytes), "r"(mbar), "h"(mask) : "memory");
}
__device__ __forceinline__ void lds128(uint4& d, uint32_t a) {
    asm volatile("ld.shared.v4.u32 {%0,%1,%2,%3}, [%4];"
                 : "=r"(d.x), "=r"(d.y), "=r"(d.z), "=r"(d.w) : "r"(a));
}
__device__ __forceinline__ unsigned lds_u8(uint32_t a) {
    unsigned v; asm volatile("ld.shared.u8 %0, [%1];" : "=r"(v) : "r"(a)); return v;
}
__device__ __forceinline__ void sts_u8(uint32_t a, unsigned v) {
    asm volatile("st.shared.u8 [%0], %1;" :: "r"(a), "r"(v) : "memory");
}
__device__ __forceinline__ int lds_s32(uint32_t a) {
    int v; asm volatile("ld.shared.b32 %0, [%1];" : "=r"(v) : "r"(a)); return v;
}

// ---------------- main kernel ----------------
__global__ __launch_bounds__(THREADS, 1) __cluster_dims__(CLUSTER, 1, 1)
void qfm_kernel(const int*   __restrict__ x,           // (B, F)
                const int*   __restrict__ cb_index,    // (F*V, 8)
                const float* __restrict__ linear_w,    // (F*V)
                const float* __restrict__ linear_bias, // (1)
                float*       __restrict__ out)         // (B)
{
    extern __shared__ char smem[];
    const uint32_t sb   = smem_u32(smem);
    const int tid  = threadIdx.x;
    const int lane = tid & 31;
    const int w    = tid >> 5;                  // warp 0..31
    const unsigned FULL = 0xffffffffu;
    const bool leader = (ctarank() == 0);

    const uint32_t full0  = sb + MBAR_OFF + 0;
    const uint32_t full1  = sb + MBAR_OFF + 8;
    const uint32_t empty0 = sb + MBAR_OFF + 16;
    const uint32_t empty1 = sb + MBAR_OFF + 24;

    // ---- init barriers + arm first two stages
    if (tid == 0) {
        MBAR_INIT(full0, 1);  MBAR_INIT(full1, 1);
        MBAR_INIT(empty0, CLUSTER); MBAR_INIT(empty1, CLUSTER);
        MBAR_EXPECT_TX(full0, SLICE_BYTES);
        MBAR_EXPECT_TX(full1, SLICE_BYTES);
    }

    // ---- stage x tile into smem (coalesced)
    const int row0g = blockIdx.x * ROWS_PER_BLOCK;     // exact fit: B = 128*128
    {
        const int* xs = x + row0g * F;
        int* xd = reinterpret_cast<int*>(smem + X_OFF);
        for (int i = tid; i < ROWS_PER_BLOCK * F; i += THREADS)
            xd[i] = xs[i];
    }
    __syncthreads();
    CLUSTER_SYNC();                                    // all CTAs armed

    // ---- leader issues first two multicast stages
    if (leader && tid == 0) {
        bulk_mcast(sb + BUF0_OFF, (const char*)g_cbh + 0 * SLICE_BYTES,
                   SLICE_BYTES, full0, 0xF);
        bulk_mcast(sb + BUF1_OFF, (const char*)g_cbh + 1 * SLICE_BYTES,
                   SLICE_BYTES, full1, 0xF);
    }

    // ---- Phase A: codes (bytes to smem) + linear accumulation.
    // Lane L: local row r = L>>3 of this warp, sub-codebook mm = L&7.
    float lin = 0.f;
    {
        const int r  = lane >> 3;
        const int mm = lane & 7;
        const int rowl = 4 * w + r;
        #pragma unroll 1
        for (int f = 0; f < F; ++f) {
            const int xi = lds_s32(sb + X_OFF + (rowl * F + f) * 4);
            const int xo = f * V + xi;
            const unsigned code = (unsigned)__ldcs(&cb_index[xo * 8 + mm]);
            sts_u8(sb + CODE_OFF + (f * ROWS_PER_BLOCK + rowl) * 8 + mm, code);
            if (mm == 0) lin += __ldcs(&linear_w[xo]);
        }
    }
    __syncthreads();                                   // codes visible

    // ---- Phase B: f-loop over staged slices.
    // Lane t: half h = t>>4 (row within pair), m = (t&15)>>1, j = t&1.
    // Pair 0 covers rows 4w + h ; pair 1 covers rows 4w + 2 + h.
    const int h = lane >> 4;
    const int m = (lane & 15) >> 1;
    const int j = lane & 1;
    const uint32_t seg_off = (uint32_t)((m << 5) + (j << 4));
    const int rA = 4 * w + h;          // local row, pair 0
    const int rB = rA + 2;             // local row, pair 1

    float s0[8], q0[8], s1[8], q1[8];
    #pragma unroll
    for (int k = 0; k < 8; ++k) { s0[k]=0.f; q0[k]=0.f; s1[k]=0.f; q1[k]=0.f; }

    #pragma unroll 1
    for (int f = 0; f < F; ++f) {
        const int slot = f & 1;
        const uint32_t fullb  = slot ? full1  : full0;
        const uint32_t emptyb = slot ? empty1 : empty0;
        const uint32_t parity = (uint32_t)((f >> 1) & 1);
        mbar_wait(fullb, parity);

        const uint32_t buf = sb + (slot ? BUF1_OFF : BUF0_OFF);
        const uint32_t cbase = sb + CODE_OFF + (uint32_t)f * (ROWS_PER_BLOCK * 8);

        const unsigned cA = lds_u8(cbase + rA * 8 + m);
        const unsigned cB = lds_u8(cbase + rB * 8 + m);
        uint4 dA, dB;
        lds128(dA, buf + (cA << 8) + seg_off);
        lds128(dB, buf + (cB << 8) + seg_off);

        const unsigned* pa = reinterpret_cast<const unsigned*>(&dA);
        const unsigned* pb = reinterpret_cast<const unsigned*>(&dB);
        #pragma unroll
        for (int k = 0; k < 4; ++k) {
            const float2 ea = __half22float2(bits_h2(pa[k]));
            s0[2*k]   += ea.x;  s0[2*k+1] += ea.y;
            q0[2*k]   = fmaf(ea.x, ea.x, q0[2*k]);
            q0[2*k+1] = fmaf(ea.y, ea.y, q0[2*k+1]);
            const float2 eb = __half22float2(bits_h2(pb[k]));
            s1[2*k]   += eb.x;  s1[2*k+1] += eb.y;
            q1[2*k]   = fmaf(eb.x, eb.x, q1[2*k]);
            q1[2*k+1] = fmaf(eb.y, eb.y, q1[2*k+1]);
        }

        __syncthreads();                               // block done with buf
        if (tid == 0) {
            if (f + 2 < F) MBAR_EXPECT_TX(fullb, SLICE_BYTES);  // re-arm slot
            MBAR_ARRIVE_RANK0(emptyb);                 // tell leader we're done
            if (leader && f + 2 < F) {
                mbar_wait(emptyb, parity);             // all 4 CTAs done
                bulk_mcast(buf, (const char*)g_cbh + (size_t)(f + 2) * SLICE_BYTES,
                           SLICE_BYTES, fullb, 0xF);
            }
        }
    }

    // ---- epilogue: fm per lane (8 dims x 2 rows) -> half-warp reduce.
    float cA = 0.f, cB = 0.f;
    #pragma unroll
    for (int k = 0; k < 8; ++k) {
        cA += 0.5f * fmaf(s0[k], s0[k], -q0[k]);
        cB += 0.5f * fmaf(s1[k], s1[k], -q1[k]);
    }
    #pragma unroll
    for (int o = 1; o < 16; o <<= 1) {
        cA += __shfl_xor_sync(FULL, cA, o);
        cB += __shfl_xor_sync(FULL, cB, o);
    }
    // lin(row 4w+r) lives at lane 8r (Phase A layout)
    const float linA = __shfl_sync(FULL, lin, 8 * h);
    const float linB = __shfl_sync(FULL, lin, 8 * h + 16);
    if ((lane & 15) == 0) {
        const float bias = __ldg(linear_bias);
        out[row0g + rA] = cA + linA + bias;
        out[row0g + rB] = cB + linB + bias;
    }

    CLUSTER_SYNC();                                    // no early exit vs peers
}

extern "C" void kernel_launch(void* const* d_in, const int* in_sizes, int n_in,
                              void* d_out, int out_size)
{
    const int*    x         = (const int*)   d_in[0];
    const float4* codebooks = (const float4*)d_in[1];
    const int*    cb_index  = (const int*)   d_in[2];
    const float*  linear_w  = (const float*) d_in[3];
    const float*  lbias     = (const float*) d_in[4];
    float*        out       = (float*)       d_out;

    // Prologue: fp32 -> fp16 codebook conversion (L2-resident, ~1 us).
    cvt_kernel<<<(CB4 + 255) / 256, 256>>>(codebooks);

    static bool attr_set = false;
    if (!attr_set) {   // idempotent; harmless if repeated, but do once
        cudaFuncSetAttribute(qfm_kernel,
                             cudaFuncAttributeMaxDynamicSharedMemorySize,
                             SMEM_TOTAL);
        attr_set = true;
    }

    const int blocks = out_size / ROWS_PER_BLOCK;      // 16384/128 = 128
    qfm_kernel<<<blocks, THREADS, SMEM_TOTAL>>>(x, cb_index, linear_w, lbias, out);
}

// round 11
// speedup vs baseline: 1.2355x; 1.2287x over previous
#include <cuda_runtime.h>
#include <cuda_fp16.h>
#include <cstdint>

// QFM split-group design.
// out[b] = sum_f linear_w[x[b,f]+f*V] + bias
//        + 0.5 * ( ||sum_f emb[b,f]||^2 - sum_f ||emb[b,f]||^2 )
// B=16384, F=39, V=100000, D=128, K=256, M=8, Q=16.
//
// k1 cvt:    fp32 codebooks -> fp16, m-major: [f][m][code][16 halves]
// k2 codes:  warp-per-row: pack 8 codes/(b,f) -> u64, f-major; + linear sum
// k3 main:   16 groups (m x f-half) x 9 CTAs; group's tables resident in
//            SMEM (<=160KB, XOR-swizzled); gathers = LDS.128; packed f32x2
//            accumulation. Writes per-(row,group) s[16] + q partials.
// k4 reduce: combine 16 partials per row -> output.

constexpr int BB = 16384;
constexpr int F  = 39;
constexpr int V  = 100000;
constexpr int K  = 256;

constexpr int SMEM_K3 = 20 * 8192;            // 160 KB (20 tables x 8KB)

// ---- static device scratch ----
__device__ uint2 g_cbh2[F * 8 * K * 4];       // fp16 tables m-major, 2.56 MB
__device__ uint2 g_codes[F * BB];             // [f][row] packed codes, 5.1 MB
__device__ float g_lin[BB];
__device__ float g_ps[16ll * BB * 16];        // [g][row][16 dims], 16.8 MB
__device__ float g_pq[16 * BB];               // [g][row]

__device__ __forceinline__ unsigned h2_bits(__half2 h) {
    return *reinterpret_cast<unsigned*>(&h);
}
__device__ __forceinline__ __half2 bits_h2(unsigned u) {
    return *reinterpret_cast<__half2*>(&u);
}
__device__ __forceinline__ uint32_t smem_u32(const void* p) {
    uint32_t a;
    asm("{ .reg .u64 t; cvta.to.shared.u64 t, %1; cvt.u32.u64 %0, t; }"
        : "=r"(a) : "l"(p));
    return a;
}
__device__ __forceinline__ uint4 lds128v(uint32_t a) {
    uint4 d;
    asm volatile("ld.shared.v4.u32 {%0,%1,%2,%3}, [%4];"
                 : "=r"(d.x), "=r"(d.y), "=r"(d.z), "=r"(d.w) : "r"(a));
    return d;
}
__device__ __forceinline__ void sts128v(uint32_t a, uint4 v) {
    asm volatile("st.shared.v4.u32 [%0], {%1,%2,%3,%4};"
                 :: "r"(a), "r"(v.x), "r"(v.y), "r"(v.z), "r"(v.w) : "memory");
}
// swizzled offset of 16B half j of entry `code` (within one 8KB table)
__device__ __forceinline__ uint32_t swz(int code, int j) {
    return (uint32_t)(((code << 5) + (j << 4)) ^ ((code & 0x1C) << 2));
}

// ---------------- k1: fp32 -> fp16, m-major ----------------
__global__ __launch_bounds__(256)
void cvt_kernel(const float4* __restrict__ src)   // (F*K, 32) float4
{
    const int i = blockIdx.x * 256 + threadIdx.x;
    if (i >= F * K * 32) return;
    const float4 v = src[i];
    const int f    = i >> 13;              // K*32 = 8192 float4 per feature
    const int rem  = i & 8191;
    const int code = rem >> 5;
    const int word = rem & 31;
    const int m    = word >> 2;
    const int q4   = word & 3;
    uint2 o;
    o.x = h2_bits(__floats2half2_rn(v.x, v.y));
    o.y = h2_bits(__floats2half2_rn(v.z, v.w));
    g_cbh2[(((f * 8 + m) * K) + code) * 4 + q4] = o;
}

// ---------------- k2: code pack + linear ----------------
// 512 blocks x 1024 threads; warp per row (32 rows/block).
__global__ __launch_bounds__(1024)
void codes_kernel(const int*   __restrict__ x,
                  const int*   __restrict__ cb_index,
                  const float* __restrict__ linear_w)
{
    __shared__ uint2 csm[F * 32];          // [f][rowInBlock]
    const unsigned FULL = 0xffffffffu;
    const int tid  = threadIdx.x;
    const int lane = tid & 31;
    const int w    = tid >> 5;
    const int row  = blockIdx.x * 32 + w;

    const int* xrow = x + row * F;
    const int idx_lo = __ldcs(&xrow[lane]);
    const int idx_hi = (lane < F - 32) ? __ldcs(&xrow[32 + lane]) : 0;

    float lin = __ldcs(&linear_w[lane * V + idx_lo]);
    if (lane < F - 32) lin += __ldcs(&linear_w[(32 + lane) * V + idx_hi]);
    #pragma unroll
    for (int o = 16; o > 0; o >>= 1) lin += __shfl_xor_sync(FULL, lin, o);
    if (lane == 0) g_lin[row] = lin;

    // chunk c: lane (sub = lane&3 -> feature 4c+sub, mseg = lane>>2 -> m)
    const int sub  = lane & 3;
    const int mseg = lane >> 2;
    #pragma unroll
    for (int c = 0; c < 10; ++c) {
        const int fl = 4 * c + sub;
        int idxf;
        if (c < 8) idxf = __shfl_sync(FULL, idx_lo, fl);
        else       idxf = __shfl_sync(FULL, idx_hi, fl - 32);
        unsigned cv = 0;
        if (fl < F)
            cv = (unsigned)__ldcs(&cb_index[((long long)fl * V + idxf) * 8 + mseg]);
        unsigned lo = (mseg < 4)  ? (cv << (8 * mseg))       : 0u;
        unsigned hi = (mseg >= 4) ? (cv << (8 * (mseg - 4))) : 0u;
        lo |= __shfl_xor_sync(FULL, lo, 4);  hi |= __shfl_xor_sync(FULL, hi, 4);
        lo |= __shfl_xor_sync(FULL, lo, 8);  hi |= __shfl_xor_sync(FULL, hi, 8);
        lo |= __shfl_xor_sync(FULL, lo, 16); hi |= __shfl_xor_sync(FULL, hi, 16);
        if (mseg == 0 && fl < F) csm[fl * 32 + w] = make_uint2(lo, hi);
    }
    __syncthreads();

    // coalesced copy-out, f-major
    for (int i = tid; i < F * 32; i += 1024) {
        const int f = i >> 5, r = i & 31;
        g_codes[(size_t)f * BB + blockIdx.x * 32 + r] = csm[i];
    }
}

// ---------------- k3: main gather/accumulate ----------------
__global__ __launch_bounds__(1024, 1)
void main_kernel()
{
    extern __shared__ char smem[];
    const uint32_t sb = smem_u32(smem);
    const int tid = threadIdx.x;

    const int g    = blockIdx.x / 9;       // 0..15
    const int sub  = blockIdx.x % 9;       // 0..8
    const int h    = g >> 3;               // feature half
    const int m    = g & 7;                // sub-codebook
    const int fbase = h * 20;
    const int NF    = h ? 19 : 20;

    // stage this group's tables into swizzled smem
    const uint4* srct = reinterpret_cast<const uint4*>(g_cbh2);
    for (int idx = tid; idx < NF * 512; idx += 1024) {
        const int fl = idx >> 9, u = idx & 511;
        const int code = u >> 1, j = u & 1;
        const uint4 v = __ldg(&srct[(((size_t)(fbase + fl) * 8 + m) * K + code) * 2 + j]);
        sts128v(sb + fl * 8192 + swz(code, j), v);
    }
    __syncthreads();

    #pragma unroll 1
    for (int it = 0; it < 2; ++it) {
        const int row = sub * 1024 + tid + it * 9216;
        if (row >= BB) break;

        unsigned long long s8[8], q2[2];
        #pragma unroll
        for (int k = 0; k < 8; ++k) s8[k] = 0ull;
        q2[0] = 0ull; q2[1] = 0ull;

        uint2 cbuf[4];
        #pragma unroll
        for (int p = 0; p < 4; ++p)
            cbuf[p] = __ldg(&g_codes[(size_t)(fbase + p) * BB + row]);

        #pragma unroll 2
        for (int fl = 0; fl < NF; ++fl) {
            const uint2 cw = cbuf[fl & 3];
            if (fl + 4 < NF)
                cbuf[fl & 3] = __ldg(&g_codes[(size_t)(fbase + fl + 4) * BB + row]);
            const unsigned code =
                ((m < 4) ? (cw.x >> (8 * m)) : (cw.y >> (8 * (m - 4)))) & 0xFFu;
            const uint32_t base = sb + fl * 8192;
            const uint4 d0 = lds128v(base + swz((int)code, 0));
            const uint4 d1 = lds128v(base + swz((int)code, 1));
            const unsigned wd[8] = {d0.x, d0.y, d0.z, d0.w,
                                    d1.x, d1.y, d1.z, d1.w};
            #pragma unroll
            for (int k = 0; k < 8; ++k) {
                const float2 ef = __half22float2(bits_h2(wd[k]));
                unsigned long long e64;
                asm("mov.b64 %0, {%1, %2};" : "=l"(e64) : "f"(ef.x), "f"(ef.y));
                asm("add.rn.f32x2 %0, %0, %1;" : "+l"(s8[k]) : "l"(e64));
                asm("fma.rn.f32x2 %0, %1, %2, %0;"
                    : "+l"(q2[k & 1]) : "l"(e64), "l"(e64));
            }
        }

        // unpack + write partials
        float sv[16];
        #pragma unroll
        for (int k = 0; k < 8; ++k)
            asm("mov.b64 {%0, %1}, %2;"
                : "=f"(sv[2 * k]), "=f"(sv[2 * k + 1]) : "l"(s8[k]));
        float qa, qb, qc, qd;
        asm("mov.b64 {%0, %1}, %2;" : "=f"(qa), "=f"(qb) : "l"(q2[0]));
        asm("mov.b64 {%0, %1}, %2;" : "=f"(qc), "=f"(qd) : "l"(q2[1]));

        float4* dst = reinterpret_cast<float4*>(g_ps + ((size_t)g * BB + row) * 16);
        dst[0] = make_float4(sv[0],  sv[1],  sv[2],  sv[3]);
        dst[1] = make_float4(sv[4],  sv[5],  sv[6],  sv[7]);
        dst[2] = make_float4(sv[8],  sv[9],  sv[10], sv[11]);
        dst[3] = make_float4(sv[12], sv[13], sv[14], sv[15]);
        g_pq[g * BB + row] = (qa + qb) + (qc + qd);
    }
}

// ---------------- k4: reduce ----------------
// 1024 blocks x 256 threads; 16 lanes per row, 2 rows/warp, 16 rows/block.
__global__ __launch_bounds__(256)
void reduce_kernel(const float* __restrict__ linear_bias,
                   float*       __restrict__ out)
{
    const unsigned FULL = 0xffffffffu;
    const int lane = threadIdx.x & 31;
    const int w    = threadIdx.x >> 5;
    const int row  = blockIdx.x * 16 + w * 2 + (lane >> 4);
    const int ld   = lane & 15;

    float acc = 0.f;
    #pragma unroll
    for (int mi = 0; mi < 8; ++mi) {
        const float a = __ldg(&g_ps[((size_t)mi * BB + row) * 16 + ld])
                      + __ldg(&g_ps[((size_t)(8 + mi) * BB + row) * 16 + ld]);
        acc = fmaf(a, a, acc);
    }
    float t = acc - __ldg(&g_pq[ld * BB + row]);
    #pragma unroll
    for (int o = 8; o > 0; o >>= 1)
        t += __shfl_xor_sync(FULL, t, o);

    if (ld == 0)
        out[row] = 0.5f * t + g_lin[row] + __ldg(linear_bias);
}

extern "C" void kernel_launch(void* const* d_in, const int* in_sizes, int n_in,
                              void* d_out, int out_size)
{
    const int*    x         = (const int*)   d_in[0];
    const float4* codebooks = (const float4*)d_in[1];
    const int*    cb_index  = (const int*)   d_in[2];
    const float*  linear_w  = (const float*) d_in[3];
    const float*  lbias     = (const float*) d_in[4];
    float*        out       = (float*)       d_out;

    static bool attr_set = false;
    if (!attr_set) {
        cudaFuncSetAttribute(main_kernel,
                             cudaFuncAttributeMaxDynamicSharedMemorySize,
                             SMEM_K3);
        attr_set = true;
    }

    cvt_kernel<<<(F * K * 32 + 255) / 256, 256>>>(codebooks);
    codes_kernel<<<BB / 32, 1024>>>(x, cb_index, linear_w);
    main_kernel<<<16 * 9, 1024, SMEM_K3>>>();
    reduce_kernel<<<BB / 16, 256>>>(lbias, out);
}

// round 12
// speedup vs baseline: 1.3291x; 1.0757x over previous
#include <cuda_runtime.h>
#include <cuda_fp16.h>
#include <cstdint>

// QFM split-group v2.
// out[b] = sum_f linear_w[x[b,f]+f*V] + bias
//        + 0.5 * ( ||sum_f emb[b,f]||^2 - sum_f ||emb[b,f]||^2 )
// B=16384, F=39, V=100000, D=128, K=256, M=8, Q=16.
//
// k1 cvt:    fp32 codebooks -> fp16, m-major [f][m][code][16 halves]
// k2 codes:  warp-per-row: pack 8 codes/(b,f) -> u64, f-major; + linear sum
// k3 main:   16 groups (m x f-half) x 9 CTAs; tables resident in SMEM
//            (160KB, bank-swizzled). Warp-instr = 16 rows x 2 half-segs,
//            lane (row,j) does one LDS.128. f32x2 packed accumulation.
// k4 reduce: 16 lanes/row combine the 16 partials -> output.

constexpr int BB = 16384;
constexpr int F  = 39;
constexpr int V  = 100000;
constexpr int K  = 256;

constexpr int SUBS      = 9;            // CTAs per group
constexpr int SUBROWS   = 1824;         // rows per sub-CTA (9*1824 >= BB)
constexpr int NCHUNK    = SUBROWS / 16; // 114 sixteen-row chunks
constexpr int SMEM_K3   = 20 * 8192;    // 160 KB

// ---- static device scratch ----
__device__ uint2 g_cbh2[F * 8 * K * 4];   // fp16 tables m-major, 2.56 MB
__device__ uint2 g_codes[F * BB];         // [f][row] packed codes, 5.1 MB
__device__ float g_lin[BB];
__device__ float g_ps[(size_t)BB * 16 * 16]; // [row][g][16 dims], 16.8 MB
__device__ float g_pq[16 * BB];              // [g][row]

__device__ __forceinline__ unsigned h2_bits(__half2 h) {
    return *reinterpret_cast<unsigned*>(&h);
}
__device__ __forceinline__ __half2 bits_h2(unsigned u) {
    return *reinterpret_cast<__half2*>(&u);
}
__device__ __forceinline__ uint32_t smem_u32(const void* p) {
    uint32_t a;
    asm("{ .reg .u64 t; cvta.to.shared.u64 t, %1; cvt.u32.u64 %0, t; }"
        : "=r"(a) : "l"(p));
    return a;
}
__device__ __forceinline__ uint4 lds128v(uint32_t a) {
    uint4 d;
    asm volatile("ld.shared.v4.u32 {%0,%1,%2,%3}, [%4];"
                 : "=r"(d.x), "=r"(d.y), "=r"(d.z), "=r"(d.w) : "r"(a));
    return d;
}
__device__ __forceinline__ void sts128v(uint32_t a, uint4 v) {
    asm volatile("st.shared.v4.u32 [%0], {%1,%2,%3,%4};"
                 :: "r"(a), "r"(v.x), "r"(v.y), "r"(v.z), "r"(v.w) : "memory");
}
// swizzled offset of 16B half j of entry `code` within one 8KB table;
// quad bits[4:6] = {j^c2, c0^c3, c1^c4} -> j always splits quads.
__device__ __forceinline__ uint32_t swz(int code, int j) {
    return (uint32_t)(((code << 5) + (j << 4)) ^ ((code & 0x1C) << 2));
}

// ---------------- k1: fp32 -> fp16, m-major ----------------
__global__ __launch_bounds__(256)
void cvt_kernel(const float4* __restrict__ src)   // (F*K, 32) float4
{
    const int i = blockIdx.x * 256 + threadIdx.x;
    if (i >= F * K * 32) return;
    const float4 v = src[i];
    const int f    = i >> 13;              // 8192 float4 per feature
    const int rem  = i & 8191;
    const int code = rem >> 5;
    const int word = rem & 31;
    const int m    = word >> 2;
    const int q4   = word & 3;
    uint2 o;
    o.x = h2_bits(__floats2half2_rn(v.x, v.y));
    o.y = h2_bits(__floats2half2_rn(v.z, v.w));
    g_cbh2[(((f * 8 + m) * K) + code) * 4 + q4] = o;
}

// ---------------- k2: code pack + linear ----------------
__global__ __launch_bounds__(1024)
void codes_kernel(const int*   __restrict__ x,
                  const int*   __restrict__ cb_index,
                  const float* __restrict__ linear_w)
{
    __shared__ uint2 csm[F * 32];          // [f][rowInBlock]
    const unsigned FULL = 0xffffffffu;
    const int tid  = threadIdx.x;
    const int lane = tid & 31;
    const int w    = tid >> 5;
    const int row  = blockIdx.x * 32 + w;

    const int* xrow = x + row * F;
    const int idx_lo = __ldcs(&xrow[lane]);
    const int idx_hi = (lane < F - 32) ? __ldcs(&xrow[32 + lane]) : 0;

    float lin = __ldcs(&linear_w[lane * V + idx_lo]);
    if (lane < F - 32) lin += __ldcs(&linear_w[(32 + lane) * V + idx_hi]);
    #pragma unroll
    for (int o = 16; o > 0; o >>= 1) lin += __shfl_xor_sync(FULL, lin, o);
    if (lane == 0) g_lin[row] = lin;

    const int sub  = lane & 3;
    const int mseg = lane >> 2;
    #pragma unroll
    for (int c = 0; c < 10; ++c) {
        const int fl = 4 * c + sub;
        int idxf;
        if (c < 8) idxf = __shfl_sync(FULL, idx_lo, fl);
        else       idxf = __shfl_sync(FULL, idx_hi, fl - 32);
        unsigned cv = 0;
        if (fl < F)
            cv = (unsigned)__ldcs(&cb_index[((long long)fl * V + idxf) * 8 + mseg]);
        unsigned lo = (mseg < 4)  ? (cv << (8 * mseg))       : 0u;
        unsigned hi = (mseg >= 4) ? (cv << (8 * (mseg - 4))) : 0u;
        lo |= __shfl_xor_sync(FULL, lo, 4);  hi |= __shfl_xor_sync(FULL, hi, 4);
        lo |= __shfl_xor_sync(FULL, lo, 8);  hi |= __shfl_xor_sync(FULL, hi, 8);
        lo |= __shfl_xor_sync(FULL, lo, 16); hi |= __shfl_xor_sync(FULL, hi, 16);
        if (mseg == 0 && fl < F) csm[fl * 32 + w] = make_uint2(lo, hi);
    }
    __syncthreads();

    for (int i = tid; i < F * 32; i += 1024) {
        const int f = i >> 5, r = i & 31;
        g_codes[(size_t)f * BB + blockIdx.x * 32 + r] = csm[i];
    }
}

// ---------------- k3: main gather/accumulate ----------------
__global__ __launch_bounds__(1024, 1)
void main_kernel()
{
    extern __shared__ char smem[];
    const uint32_t sb = smem_u32(smem);
    const int tid = threadIdx.x;
    const unsigned FULL = 0xffffffffu;

    const int g    = blockIdx.x / SUBS;    // 0..15
    const int sub  = blockIdx.x % SUBS;    // 0..8
    const int h    = g >> 3;               // feature half
    const int m    = g & 7;                // sub-codebook
    const int fbase = h * 20;
    const int NF    = h ? 19 : 20;

    // stage this group's tables (swizzled)
    const uint4* srct = reinterpret_cast<const uint4*>(g_cbh2);
    for (int idx = tid; idx < NF * 512; idx += 1024) {
        const int fl = idx >> 9, u = idx & 511;
        const int code = u >> 1, j = u & 1;
        const uint4 v = __ldg(&srct[(((size_t)(fbase + fl) * 8 + m) * K + code) * 2 + j]);
        sts128v(sb + fl * 8192 + swz(code, j), v);
    }
    __syncthreads();

    const int lane  = tid & 31;
    const int w     = tid >> 5;
    const int row_r = lane >> 1;           // 0..15
    const int j     = lane & 1;
    const int shf   = (m & 3) * 8;
    const bool mhi  = (m >= 4);

    #pragma unroll 1
    for (int t = 0; t < 4; ++t) {
        const int chunk = t * 32 + w;
        if (chunk >= NCHUNK) break;
        const int row0 = sub * SUBROWS + chunk * 16;
        if (row0 >= BB) break;
        const int row = row0 + row_r;

        unsigned long long s4[4] = {0ull, 0ull, 0ull, 0ull};
        unsigned long long q2[2] = {0ull, 0ull};

        uint2 cb[4];
        #pragma unroll
        for (int p = 0; p < 4; ++p)
            cb[p] = __ldg(&g_codes[(size_t)(fbase + p) * BB + row]);

        #pragma unroll 4
        for (int fl = 0; fl < 20; ++fl) {
            if (fl >= NF) break;
            const uint2 cw = cb[fl & 3];
            if (fl + 4 < NF)
                cb[fl & 3] = __ldg(&g_codes[(size_t)(fbase + fl + 4) * BB + row]);
            const unsigned code = ((mhi ? cw.y : cw.x) >> shf) & 0xFFu;
            const uint4 d = lds128v(sb + fl * 8192 + swz((int)code, j));
            const unsigned wd[4] = {d.x, d.y, d.z, d.w};
            #pragma unroll
            for (int k = 0; k < 4; ++k) {
                const float2 ef = __half22float2(bits_h2(wd[k]));
                unsigned long long e64;
                asm("mov.b64 %0, {%1, %2};" : "=l"(e64) : "f"(ef.x), "f"(ef.y));
                asm("add.rn.f32x2 %0, %0, %1;" : "+l"(s4[k]) : "l"(e64));
                asm("fma.rn.f32x2 %0, %1, %2, %0;"
                    : "+l"(q2[k & 1]) : "l"(e64), "l"(e64));
            }
        }

        // unpack + write partials (this thread: dims j*8 .. j*8+7 of m)
        float sv[8];
        #pragma unroll
        for (int k = 0; k < 4; ++k)
            asm("mov.b64 {%0, %1}, %2;"
                : "=f"(sv[2 * k]), "=f"(sv[2 * k + 1]) : "l"(s4[k]));
        float qa, qb, qc, qd;
        asm("mov.b64 {%0, %1}, %2;" : "=f"(qa), "=f"(qb) : "l"(q2[0]));
        asm("mov.b64 {%0, %1}, %2;" : "=f"(qc), "=f"(qd) : "l"(q2[1]));
        float qsum = (qa + qb) + (qc + qd);
        qsum += __shfl_xor_sync(FULL, qsum, 1);    // combine j=0/1

        float4* dst = reinterpret_cast<float4*>(
            g_ps + (((size_t)row * 16 + g) * 16 + j * 8));
        dst[0] = make_float4(sv[0], sv[1], sv[2], sv[3]);
        dst[1] = make_float4(sv[4], sv[5], sv[6], sv[7]);
        if (j == 0) g_pq[(size_t)g * BB + row] = qsum;
    }
}

// ---------------- k4: reduce ----------------
// 1024 blocks x 256 threads; 16 lanes per row, 2 rows per warp.
__global__ __launch_bounds__(256)
void reduce_kernel(const float* __restrict__ linear_bias,
                   float*       __restrict__ out)
{
    const unsigned FULL = 0xffffffffu;
    const int lane = threadIdx.x & 31;
    const int w    = threadIdx.x >> 5;
    const int row  = blockIdx.x * 16 + w * 2 + (lane >> 4);
    const int l    = lane & 15;
    const int m    = l >> 1;
    const int j    = l & 1;

    const float4* base = reinterpret_cast<const float4*>(g_ps + (size_t)row * 256);
    const float4 A0 = __ldg(base + (m * 16 + j * 8) / 4);
    const float4 A1 = __ldg(base + (m * 16 + j * 8) / 4 + 1);
    const float4 B0 = __ldg(base + ((8 + m) * 16 + j * 8) / 4);
    const float4 B1 = __ldg(base + ((8 + m) * 16 + j * 8) / 4 + 1);

    float acc = 0.f, a;
    a = A0.x + B0.x; acc = fmaf(a, a, acc);
    a = A0.y + B0.y; acc = fmaf(a, a, acc);
    a = A0.z + B0.z; acc = fmaf(a, a, acc);
    a = A0.w + B0.w; acc = fmaf(a, a, acc);
    a = A1.x + B1.x; acc = fmaf(a, a, acc);
    a = A1.y + B1.y; acc = fmaf(a, a, acc);
    a = A1.z + B1.z; acc = fmaf(a, a, acc);
    a = A1.w + B1.w; acc = fmaf(a, a, acc);

    acc -= __ldg(&g_pq[(size_t)l * BB + row]);     // 16 lanes cover 16 groups

    #pragma unroll
    for (int o = 8; o > 0; o >>= 1)
        acc += __shfl_xor_sync(FULL, acc, o);

    if (l == 0)
        out[row] = 0.5f * acc + g_lin[row] + __ldg(linear_bias);
}

extern "C" void kernel_launch(void* const* d_in, const int* in_sizes, int n_in,
                              void* d_out, int out_size)
{
    const int*    x         = (const int*)   d_in[0];
    const float4* codebooks = (const float4*)d_in[1];
    const int*    cb_index  = (const int*)   d_in[2];
    const float*  linear_w  = (const float*) d_in[3];
    const float*  lbias     = (const float*) d_in[4];
    float*        out       = (float*)       d_out;

    static bool attr_set = false;
    if (!attr_set) {
        cudaFuncSetAttribute(main_kernel,
                             cudaFuncAttributeMaxDynamicSharedMemorySize,
                             SMEM_K3);
        attr_set = true;
    }

    cvt_kernel<<<(F * K * 32 + 255) / 256, 256>>>(codebooks);
    codes_kernel<<<BB / 32, 1024>>>(x, cb_index, linear_w);
    main_kernel<<<16 * SUBS, 1024, SMEM_K3>>>();
    reduce_kernel<<<BB / 16, 256>>>(lbias, out);
}